// round 14
// baseline (speedup 1.0000x reference)
#include <cuda_runtime.h>
#include <cuda_bf16.h>
#include <cstdint>

#define SL 256        // syndrome bit length (fixed for this problem family)
#define NB 8192       // hash-table slots (power of 2, load factor <= 0.5)

// Scratch (no allocation allowed). Zero-init == empty table.
// g_sidx[slot]: 0 = empty, else entry_index + 1.
// g_skey[slot]: full 256-bit (ballot-order) key for that slot.
// Inserts are idempotent across graph replays.
__device__ unsigned int g_sidx[NB];
__device__ uint4        g_skey[NB * 2];   // 2 x uint4 = 32B per slot

// Cheap 32-bit hash over the 8 ballot words. Keys are uniform random bits,
// so xor-fold + 2 multiplies gives uniform buckets. Correctness never
// depends on this (full 256-bit verify below).
__device__ __forceinline__ unsigned hash8(const uint32_t* w) {
    unsigned h = (w[0] ^ w[1] ^ w[2] ^ w[3]) * 0x9E3779B9u
               ^ (w[4] ^ w[5] ^ w[6] ^ w[7]) * 0x85EBCA6Bu;
    h ^= h >> 13;
    h *= 0xC2B2AE35u;
    h ^= h >> 16;
    return h;
}

// Warp-cooperative pack via float4: 2 LDG.128 per lane + 8 ballots.
// Fixed bit permutation; build and lookup use the identical function, so
// exact-match equality is preserved.
__device__ __forceinline__ void pack_row_f4(const float* __restrict__ row,
                                            int lane, uint32_t* w) {
    const float4* r4 = (const float4*)row;
    float4 a = __ldg(r4 + lane);
    float4 b = __ldg(r4 + lane + 32);
    const unsigned m = 0xffffffffu;
    w[0] = __ballot_sync(m, a.x > 0.5f);
    w[1] = __ballot_sync(m, a.y > 0.5f);
    w[2] = __ballot_sync(m, a.z > 0.5f);
    w[3] = __ballot_sync(m, a.w > 0.5f);
    w[4] = __ballot_sync(m, b.x > 0.5f);
    w[5] = __ballot_sync(m, b.y > 0.5f);
    w[6] = __ballot_sync(m, b.z > 0.5f);
    w[7] = __ballot_sync(m, b.w > 0.5f);
}

__device__ __forceinline__ bool key_eq(uint4 a, uint4 b, const uint32_t* w) {
    return a.x == w[0] && a.y == w[1] && a.z == w[2] && a.w == w[3] &&
           b.x == w[4] && b.y == w[5] && b.z == w[6] && b.w == w[7];
}

// ---------------------------------------------------------------------------
// Kernel 1: build. One warp per table row; insert idx+1 + packed key.
// ---------------------------------------------------------------------------
__global__ __launch_bounds__(256) void build_table_kernel(
    const float* __restrict__ tk, int T)
{
    int row_i = (blockIdx.x * blockDim.x + threadIdx.x) >> 5;
    int lane  = threadIdx.x & 31;
    if (row_i >= T) return;

    uint32_t w[8];
    pack_row_f4(tk + (size_t)row_i * SL, lane, w);

    if (lane == 0) {
        unsigned b = hash8(w) & (NB - 1);
        unsigned tag = (unsigned)row_i + 1u;
        for (;;) {
            unsigned prev = atomicCAS(&g_sidx[b], 0u, tag);
            if (prev == 0u || prev == tag) break;       // idempotent on replay
            b = (b + 1) & (NB - 1);
        }
        g_skey[b * 2]     = make_uint4(w[0], w[1], w[2], w[3]);
        g_skey[b * 2 + 1] = make_uint4(w[4], w[5], w[6], w[7]);
    }
}

// Rare continuation: cluster longer than 32 slots (essentially never at 25% load).
__device__ __noinline__ int probe_more(unsigned b, int lane, const uint32_t* w)
{
    int best = 0x7fffffff;
    for (;;) {
        unsigned slot = (b + lane) & (NB - 1);
        unsigned s = __ldg(&g_sidx[slot]);
        unsigned empty = __ballot_sync(0xffffffffu, s == 0u);
        int fe = empty ? (__ffs(empty) - 1) : 32;
        if (s != 0u && lane < fe) {
            uint4 ka = __ldg(&g_skey[slot * 2]);
            uint4 kb = __ldg(&g_skey[slot * 2 + 1]);
            if (key_eq(ka, kb, w))
                best = min(best, (int)s - 1);
        }
        if (fe < 32) break;
        b = (b + 32) & (NB - 1);
    }
    return best;
}

// ---------------------------------------------------------------------------
// Kernel 2: lookup. One warp per query, 256-thread blocks (grid ~1024 for
// near-perfect SM balance). Single-hop probe: slot-keyed keys let the verify
// loads issue in parallel with the slot-index loads.
// ---------------------------------------------------------------------------
__global__ __launch_bounds__(256) void lookup_kernel(
    const float* __restrict__ syn,
    const float* __restrict__ tv,
    float* __restrict__ out,
    int B)
{
    const int lane = threadIdx.x & 31;
    const int q = blockIdx.x * (blockDim.x >> 5) + (threadIdx.x >> 5);
    if (q >= B) return;

    uint32_t w[8];
    pack_row_f4(syn + (size_t)q * SL, lane, w);
    unsigned b0 = hash8(w) & (NB - 1);

    // ---- Single-hop warp-parallel probe ----
    unsigned slot = (b0 + lane) & (NB - 1);
    unsigned s = __ldg(&g_sidx[slot]);

    // Speculative key loads on lanes 0..7 (clusters >8 are vanishingly rare);
    // the address depends only on the slot, so these issue alongside sidx.
    uint4 ka, kb;
    bool spec = (lane < 8);
    if (spec) {
        ka = __ldg(&g_skey[slot * 2]);
        kb = __ldg(&g_skey[slot * 2 + 1]);
    }

    unsigned empty = __ballot_sync(0xffffffffu, s == 0u);
    int fe = empty ? (__ffs(empty) - 1) : 32;

    int best = 0x7fffffff;
    if (s != 0u && lane < fe) {
        if (!spec) {   // rare dependent fallback for lanes 8..fe-1
            ka = __ldg(&g_skey[slot * 2]);
            kb = __ldg(&g_skey[slot * 2 + 1]);
        }
        if (key_eq(ka, kb, w))
            best = (int)s - 1;                        // first match = min idx
    }
    if (fe == 32)
        best = min(best, probe_more((b0 + 32) & (NB - 1), lane, w));

    best = (int)__reduce_min_sync(0xffffffffu, (unsigned)best);

    // ---- Vectorized emit: 256 floats = 64 float4; 2 per lane ----
    float4* orow4 = (float4*)(out + (size_t)q * SL);
    if (best != 0x7fffffff) {
        const float4* vr = (const float4*)(tv + (size_t)best * SL);
        float4 a = __ldg(vr + lane);
        float4 c = __ldg(vr + lane + 32);
        orow4[lane]      = a;
        orow4[lane + 32] = c;
    } else {
        float4 z = make_float4(0.f, 0.f, 0.f, 0.f);
        orow4[lane]      = z;
        orow4[lane + 32] = z;
    }
}

// ---------------------------------------------------------------------------
extern "C" void kernel_launch(void* const* d_in, const int* in_sizes, int n_in,
                              void* d_out, int out_size) {
    const float* syn = (const float*)d_in[0];   // [B, 256]
    const float* tk  = (const float*)d_in[1];   // [T, 256]
    const float* tv  = (const float*)d_in[2];   // [T, 256]
    float* out = (float*)d_out;                 // [B, 256]

    int B = in_sizes[0] / SL;
    int T = in_sizes[1] / SL;

    build_table_kernel<<<(T + 7) / 8, 256>>>(tk, T);
    // 256 threads = 8 warps/block, 1 query/warp -> grid 1024 (balanced wave).
    lookup_kernel<<<(B + 7) / 8, 256>>>(syn, tv, out, B);
}

// round 16
// speedup vs baseline: 1.0175x; 1.0175x over previous
#include <cuda_runtime.h>
#include <cuda_bf16.h>
#include <cstdint>

#define SL 256        // syndrome bit length (fixed for this problem family)
#define NB 8192       // hash-table slots (power of 2, load factor <= 0.5)

// Scratch (no allocation allowed). Zero-init == empty table.
// g_sidx[slot]: 0 = empty, else entry_index + 1.
// g_skey[slot]: full 256-bit (ballot-order) key for that slot.
// Inserts are idempotent across graph replays.
__device__ unsigned int g_sidx[NB];
__device__ ulonglong4   g_skey[NB];

// Cheap 32-bit hash over the 8 ballot words (uniform random bits -> uniform
// buckets). Correctness never depends on it: full 256-bit verify below.
__device__ __forceinline__ unsigned hash8(const uint32_t* w) {
    unsigned h = (w[0] ^ w[1] ^ w[2] ^ w[3]) * 0x9E3779B9u
               ^ (w[4] ^ w[5] ^ w[6] ^ w[7]) * 0x85EBCA6Bu;
    h ^= h >> 13;
    h *= 0xC2B2AE35u;
    h ^= h >> 16;
    return h;
}

// Warp-cooperative pack via float4: 2 LDG.128 per lane + 8 ballots.
// Fixed bit permutation; build and lookup use the identical function, so
// exact-match equality is preserved. Outputs both the raw words (for the
// hash) and the combined u64s (for the verify compare).
__device__ __forceinline__ void pack_row_f4(const float* __restrict__ row,
                                            int lane, uint32_t* w,
                                            uint64_t& k0, uint64_t& k1,
                                            uint64_t& k2, uint64_t& k3) {
    const float4* r4 = (const float4*)row;
    float4 a = __ldg(r4 + lane);
    float4 b = __ldg(r4 + lane + 32);
    const unsigned m = 0xffffffffu;
    w[0] = __ballot_sync(m, a.x > 0.5f);
    w[1] = __ballot_sync(m, a.y > 0.5f);
    w[2] = __ballot_sync(m, a.z > 0.5f);
    w[3] = __ballot_sync(m, a.w > 0.5f);
    w[4] = __ballot_sync(m, b.x > 0.5f);
    w[5] = __ballot_sync(m, b.y > 0.5f);
    w[6] = __ballot_sync(m, b.z > 0.5f);
    w[7] = __ballot_sync(m, b.w > 0.5f);
    k0 = (uint64_t)w[0] | ((uint64_t)w[1] << 32);
    k1 = (uint64_t)w[2] | ((uint64_t)w[3] << 32);
    k2 = (uint64_t)w[4] | ((uint64_t)w[5] << 32);
    k3 = (uint64_t)w[6] | ((uint64_t)w[7] << 32);
}

// ---------------------------------------------------------------------------
// Kernel 1: build. One warp per table row; insert idx+1 + packed key.
// ---------------------------------------------------------------------------
__global__ __launch_bounds__(256) void build_table_kernel(
    const float* __restrict__ tk, int T)
{
    int row_i = (blockIdx.x * blockDim.x + threadIdx.x) >> 5;
    int lane  = threadIdx.x & 31;
    if (row_i >= T) return;

    uint32_t w[8];
    uint64_t k0, k1, k2, k3;
    pack_row_f4(tk + (size_t)row_i * SL, lane, w, k0, k1, k2, k3);

    if (lane == 0) {
        unsigned b = hash8(w) & (NB - 1);
        unsigned tag = (unsigned)row_i + 1u;
        for (;;) {
            unsigned prev = atomicCAS(&g_sidx[b], 0u, tag);
            if (prev == 0u || prev == tag) break;       // idempotent on replay
            b = (b + 1) & (NB - 1);
        }
        ulonglong2* kp = (ulonglong2*)&g_skey[b];
        kp[0] = make_ulonglong2(k0, k1);
        kp[1] = make_ulonglong2(k2, k3);
    }
}

// Rare continuation: cluster longer than 32 slots (essentially never at 25% load).
__device__ __noinline__ int probe_more(unsigned b, int lane,
    uint64_t q0, uint64_t q1, uint64_t q2, uint64_t q3)
{
    int best = 0x7fffffff;
    for (;;) {
        unsigned slot = (b + lane) & (NB - 1);
        unsigned s = __ldg(&g_sidx[slot]);
        unsigned empty = __ballot_sync(0xffffffffu, s == 0u);
        int fe = empty ? (__ffs(empty) - 1) : 32;
        if (s != 0u && lane < fe) {
            const ulonglong2* kp = (const ulonglong2*)&g_skey[slot];
            ulonglong2 a = __ldg(kp);
            ulonglong2 c = __ldg(kp + 1);
            if (a.x == q0 && a.y == q1 && c.x == q2 && c.y == q3)
                best = min(best, (int)s - 1);
        }
        if (fe < 32) break;
        b = (b + 32) & (NB - 1);
    }
    return best;
}

// ---------------------------------------------------------------------------
// Kernel 2: lookup. One warp per query; 512-thread blocks (16 warps) —
// the proven-fastest geometry. Single-hop probe: slot-keyed keys let the
// verify loads issue in parallel with the slot-index loads.
// ---------------------------------------------------------------------------
__global__ __launch_bounds__(512) void lookup_kernel(
    const float* __restrict__ syn,
    const float* __restrict__ tv,
    float* __restrict__ out,
    int B)
{
    const int lane = threadIdx.x & 31;
    const int q = blockIdx.x * (blockDim.x >> 5) + (threadIdx.x >> 5);
    if (q >= B) return;

    uint32_t w[8];
    uint64_t q0, q1, q2, q3;
    pack_row_f4(syn + (size_t)q * SL, lane, w, q0, q1, q2, q3);
    unsigned b0 = hash8(w) & (NB - 1);

    // ---- Single-hop warp-parallel probe ----
    unsigned slot = (b0 + lane) & (NB - 1);
    unsigned s = __ldg(&g_sidx[slot]);

    // Speculative key loads on lanes 0..7 (clusters >8 are vanishingly rare);
    // the address depends only on the slot, so these issue alongside sidx.
    ulonglong2 ka, kc;
    bool spec = (lane < 8);
    if (spec) {
        const ulonglong2* kp = (const ulonglong2*)&g_skey[slot];
        ka = __ldg(kp);
        kc = __ldg(kp + 1);
    }

    unsigned empty = __ballot_sync(0xffffffffu, s == 0u);
    int fe = empty ? (__ffs(empty) - 1) : 32;

    int best = 0x7fffffff;
    if (s != 0u && lane < fe) {
        if (!spec) {   // rare dependent fallback for lanes 8..fe-1
            const ulonglong2* kp = (const ulonglong2*)&g_skey[slot];
            ka = __ldg(kp);
            kc = __ldg(kp + 1);
        }
        if (ka.x == q0 && ka.y == q1 && kc.x == q2 && kc.y == q3)
            best = (int)s - 1;                        // first match = min idx
    }
    if (fe == 32)
        best = min(best, probe_more((b0 + 32) & (NB - 1), lane, q0, q1, q2, q3));

    best = (int)__reduce_min_sync(0xffffffffu, (unsigned)best);

    // ---- Vectorized emit: 256 floats = 64 float4; 2 per lane ----
    float4* orow4 = (float4*)(out + (size_t)q * SL);
    if (best != 0x7fffffff) {
        const float4* vr = (const float4*)(tv + (size_t)best * SL);
        float4 a = __ldg(vr + lane);
        float4 c = __ldg(vr + lane + 32);
        orow4[lane]      = a;
        orow4[lane + 32] = c;
    } else {
        float4 z = make_float4(0.f, 0.f, 0.f, 0.f);
        orow4[lane]      = z;
        orow4[lane + 32] = z;
    }
}

// ---------------------------------------------------------------------------
extern "C" void kernel_launch(void* const* d_in, const int* in_sizes, int n_in,
                              void* d_out, int out_size) {
    const float* syn = (const float*)d_in[0];   // [B, 256]
    const float* tk  = (const float*)d_in[1];   // [T, 256]
    const float* tv  = (const float*)d_in[2];   // [T, 256]
    float* out = (float*)d_out;                 // [B, 256]

    int B = in_sizes[0] / SL;
    int T = in_sizes[1] / SL;

    build_table_kernel<<<(T + 7) / 8, 256>>>(tk, T);
    // 512 threads = 16 warps/block, 1 query/warp (proven-best geometry).
    lookup_kernel<<<(B + 15) / 16, 512>>>(syn, tv, out, B);
}

// round 17
// speedup vs baseline: 1.2186x; 1.1976x over previous
#include <cuda_runtime.h>
#include <cuda_bf16.h>
#include <cstdint>

#define SL 256        // syndrome bit length (fixed for this problem family)
#define NB 8192       // hash-table slots (power of 2, load factor <= 0.5)

// Scratch (no allocation allowed). Zero-init == empty table.
// g_sidx[slot]: 0 = empty, else entry_index + 1.
// g_skey[slot]: full 256-bit (ballot-order) key for that slot.
// Inserts are idempotent across graph replays.
__device__ unsigned int g_sidx[NB];
__device__ ulonglong4   g_skey[NB];

// Cheap 32-bit hash over the 8 ballot words (uniform random bits -> uniform
// buckets). Correctness never depends on it: full 256-bit verify below.
__device__ __forceinline__ unsigned hash8(const uint32_t* w) {
    unsigned h = (w[0] ^ w[1] ^ w[2] ^ w[3]) * 0x9E3779B9u
               ^ (w[4] ^ w[5] ^ w[6] ^ w[7]) * 0x85EBCA6Bu;
    h ^= h >> 13;
    h *= 0xC2B2AE35u;
    h ^= h >> 16;
    return h;
}

// Warp-cooperative pack via float4: 2 LDG.128 per lane + 8 ballots.
// Fixed bit permutation; build and lookup use the identical function, so
// exact-match equality is preserved. Outputs both the raw words (for the
// hash) and the combined u64s (for the verify compare).
__device__ __forceinline__ void pack_row_f4(const float* __restrict__ row,
                                            int lane, uint32_t* w,
                                            uint64_t& k0, uint64_t& k1,
                                            uint64_t& k2, uint64_t& k3) {
    const float4* r4 = (const float4*)row;
    float4 a = __ldg(r4 + lane);
    float4 b = __ldg(r4 + lane + 32);
    const unsigned m = 0xffffffffu;
    w[0] = __ballot_sync(m, a.x > 0.5f);
    w[1] = __ballot_sync(m, a.y > 0.5f);
    w[2] = __ballot_sync(m, a.z > 0.5f);
    w[3] = __ballot_sync(m, a.w > 0.5f);
    w[4] = __ballot_sync(m, b.x > 0.5f);
    w[5] = __ballot_sync(m, b.y > 0.5f);
    w[6] = __ballot_sync(m, b.z > 0.5f);
    w[7] = __ballot_sync(m, b.w > 0.5f);
    k0 = (uint64_t)w[0] | ((uint64_t)w[1] << 32);
    k1 = (uint64_t)w[2] | ((uint64_t)w[3] << 32);
    k2 = (uint64_t)w[4] | ((uint64_t)w[5] << 32);
    k3 = (uint64_t)w[6] | ((uint64_t)w[7] << 32);
}

// ---------------------------------------------------------------------------
// Kernel 1: build. One warp per table row; insert idx+1 + packed key.
// ---------------------------------------------------------------------------
__global__ __launch_bounds__(256) void build_table_kernel(
    const float* __restrict__ tk, int T)
{
    int row_i = (blockIdx.x * blockDim.x + threadIdx.x) >> 5;
    int lane  = threadIdx.x & 31;
    if (row_i >= T) return;

    uint32_t w[8];
    uint64_t k0, k1, k2, k3;
    pack_row_f4(tk + (size_t)row_i * SL, lane, w, k0, k1, k2, k3);

    if (lane == 0) {
        unsigned b = hash8(w) & (NB - 1);
        unsigned tag = (unsigned)row_i + 1u;
        for (;;) {
            unsigned prev = atomicCAS(&g_sidx[b], 0u, tag);
            if (prev == 0u || prev == tag) break;       // idempotent on replay
            b = (b + 1) & (NB - 1);
        }
        ulonglong2* kp = (ulonglong2*)&g_skey[b];
        kp[0] = make_ulonglong2(k0, k1);
        kp[1] = make_ulonglong2(k2, k3);
    }
}

// Rare continuation: cluster longer than 32 slots (essentially never at 25% load).
__device__ __noinline__ int probe_more(unsigned b, int lane,
    uint64_t q0, uint64_t q1, uint64_t q2, uint64_t q3)
{
    int best = 0x7fffffff;
    for (;;) {
        unsigned slot = (b + lane) & (NB - 1);
        unsigned s = __ldg(&g_sidx[slot]);
        unsigned empty = __ballot_sync(0xffffffffu, s == 0u);
        int fe = empty ? (__ffs(empty) - 1) : 32;
        if (s != 0u && lane < fe) {
            const ulonglong2* kp = (const ulonglong2*)&g_skey[slot];
            ulonglong2 a = __ldg(kp);
            ulonglong2 c = __ldg(kp + 1);
            if (a.x == q0 && a.y == q1 && c.x == q2 && c.y == q3)
                best = min(best, (int)s - 1);
        }
        if (fe < 32) break;
        b = (b + 32) & (NB - 1);
    }
    return best;
}

// ---------------------------------------------------------------------------
// Kernel 2: lookup. One warp per query; 128-thread blocks (grid 2048) for
// near-uniform SM load (14 vs 13 blocks/SM = 7% imbalance, vs 33% at 512thr).
// Single-hop probe: slot-keyed keys let the verify loads issue in parallel
// with the slot-index loads.
// ---------------------------------------------------------------------------
__global__ __launch_bounds__(128) void lookup_kernel(
    const float* __restrict__ syn,
    const float* __restrict__ tv,
    float* __restrict__ out,
    int B)
{
    const int lane = threadIdx.x & 31;
    const int q = blockIdx.x * (blockDim.x >> 5) + (threadIdx.x >> 5);
    if (q >= B) return;

    uint32_t w[8];
    uint64_t q0, q1, q2, q3;
    pack_row_f4(syn + (size_t)q * SL, lane, w, q0, q1, q2, q3);
    unsigned b0 = hash8(w) & (NB - 1);

    // ---- Single-hop warp-parallel probe ----
    unsigned slot = (b0 + lane) & (NB - 1);
    unsigned s = __ldg(&g_sidx[slot]);

    // Speculative key loads on lanes 0..7 (clusters >8 are vanishingly rare);
    // the address depends only on the slot, so these issue alongside sidx.
    ulonglong2 ka, kc;
    bool spec = (lane < 8);
    if (spec) {
        const ulonglong2* kp = (const ulonglong2*)&g_skey[slot];
        ka = __ldg(kp);
        kc = __ldg(kp + 1);
    }

    unsigned empty = __ballot_sync(0xffffffffu, s == 0u);
    int fe = empty ? (__ffs(empty) - 1) : 32;

    int best = 0x7fffffff;
    if (s != 0u && lane < fe) {
        if (!spec) {   // rare dependent fallback for lanes 8..fe-1
            const ulonglong2* kp = (const ulonglong2*)&g_skey[slot];
            ka = __ldg(kp);
            kc = __ldg(kp + 1);
        }
        if (ka.x == q0 && ka.y == q1 && kc.x == q2 && kc.y == q3)
            best = (int)s - 1;                        // first match = min idx
    }
    if (fe == 32)
        best = min(best, probe_more((b0 + 32) & (NB - 1), lane, q0, q1, q2, q3));

    best = (int)__reduce_min_sync(0xffffffffu, (unsigned)best);

    // ---- Vectorized emit: 256 floats = 64 float4; 2 per lane ----
    float4* orow4 = (float4*)(out + (size_t)q * SL);
    if (best != 0x7fffffff) {
        const float4* vr = (const float4*)(tv + (size_t)best * SL);
        float4 a = __ldg(vr + lane);
        float4 c = __ldg(vr + lane + 32);
        orow4[lane]      = a;
        orow4[lane + 32] = c;
    } else {
        float4 z = make_float4(0.f, 0.f, 0.f, 0.f);
        orow4[lane]      = z;
        orow4[lane + 32] = z;
    }
}

// ---------------------------------------------------------------------------
extern "C" void kernel_launch(void* const* d_in, const int* in_sizes, int n_in,
                              void* d_out, int out_size) {
    const float* syn = (const float*)d_in[0];   // [B, 256]
    const float* tk  = (const float*)d_in[1];   // [T, 256]
    const float* tv  = (const float*)d_in[2];   // [T, 256]
    float* out = (float*)d_out;                 // [B, 256]

    int B = in_sizes[0] / SL;
    int T = in_sizes[1] / SL;

    build_table_kernel<<<(T + 7) / 8, 256>>>(tk, T);
    // 128 threads = 4 warps/block, 1 query/warp -> grid 2048 (balanced SMs).
    lookup_kernel<<<(B + 3) / 4, 128>>>(syn, tv, out, B);
}